// round 15
// baseline (speedup 1.0000x reference)
#include <cuda_runtime.h>
#include <math.h>

#define B 32
#define L 256
#define EXT 64
#define H 256
#define M 64
#define NMEM 4096
#define NST 32
#define OUT 64

typedef unsigned long long ull;

// ---------------- scratch (device globals; no allocation) ----------------
__device__ float g_xm[B * H];
__device__ float g_kw[B * M], g_e[B * M], g_a[B * M], g_kr[B * M];
__device__ float g_pw[B * 8], g_pr[B * 8];
__device__ __align__(16) float g_score[B * NMEM];
__device__ __align__(16) float g_st2[(size_t)B * NMEM * 8];  // d1,d2,ss,s2 | s3,s4,s5,_
__device__ __align__(16) float g_ww[B * NMEM];
__device__ __align__(16) float g_wr[B * NMEM];
__device__ float g_rpart[B * 32 * M];
__device__ int g_cntR[B];

// ---------------- helpers ----------------
__device__ __forceinline__ float wredsum(float v) {
    #pragma unroll
    for (int o = 16; o > 0; o >>= 1) v += __shfl_xor_sync(0xffffffffu, v, o);
    return v;
}
__device__ __forceinline__ float gredsum16(float v) {
    #pragma unroll
    for (int o = 8; o > 0; o >>= 1) v += __shfl_xor_sync(0xffffffffu, v, o);
    return v;
}
__device__ __forceinline__ float wredmax(float v) {
    #pragma unroll
    for (int o = 16; o > 0; o >>= 1) v = fmaxf(v, __shfl_xor_sync(0xffffffffu, v, o));
    return v;
}
__device__ __forceinline__ float softplus_f(float x) {
    return (x > 20.f) ? x : log1pf(expf(x));
}
__device__ __forceinline__ float sigmoid_f(float x) {
    return 1.f / (1.f + expf(-x));
}
__device__ __forceinline__ ull pack2(float lo, float hi) {
    ull r; asm("mov.b64 %0,{%1,%2};" : "=l"(r) : "f"(lo), "f"(hi)); return r;
}
__device__ __forceinline__ void unpack2(ull v, float& lo, float& hi) {
    asm("mov.b64 {%0,%1},%2;" : "=f"(lo), "=f"(hi) : "l"(v));
}
__device__ __forceinline__ ull f2fma(ull a, ull b, ull c) {
    ull d; asm("fma.rn.f32x2 %0,%1,%2,%3;" : "=l"(d) : "l"(a), "l"(b), "l"(c)); return d;
}
__device__ __forceinline__ ull f2mul(ull a, ull b) {
    ull d; asm("mul.rn.f32x2 %0,%1,%2;" : "=l"(d) : "l"(a), "l"(b)); return d;
}

// ============ Kernel 1: register-tiled encoder GEMM + ILP-4 S4D scan ============
__global__ void __launch_bounds__(256) k_encode_scan(
    const float* __restrict__ x, const float* __restrict__ r0,
    const float* __restrict__ sr0, const float* __restrict__ si0,
    const float* __restrict__ encW, const float* __restrict__ encb,
    const float* __restrict__ log_dt, const float* __restrict__ logAr,
    const float* __restrict__ Aim, const float* __restrict__ Cre,
    const float* __restrict__ Cim, const float* __restrict__ Dv)
{
    __shared__ float Ws[64 * 16];
    __shared__ float cbs[16];
    __shared__ __align__(16) float xsT[16 * 264];
    __shared__ __align__(16) float us[16 * 264];

    int b = blockIdx.x, hg = blockIdx.y;
    int t = threadIdx.x;

    for (int i = t; i < 64 * 16; i += 256) {
        int e = i >> 4, hh = i & 15;
        Ws[i] = encW[e * H + hg * 16 + hh];
    }

    {
        int hh_b = t >> 4, p_b = t & 15;
        float cb = 0.f;
        #pragma unroll
        for (int m = p_b; m < M; m += 16)
            cb = fmaf(r0[b * M + m], encW[(EXT + m) * H + hg * 16 + hh_b], cb);
        cb = gredsum16(cb) + encb[hg * 16 + hh_b];
        if (p_b == 0) cbs[hh_b] = cb;
    }
    __syncthreads();

    int lq = t >> 2, hq = t & 3;
    float acc[4][4];
    #pragma unroll
    for (int i = 0; i < 4; i++)
        #pragma unroll
        for (int j = 0; j < 4; j++) acc[i][j] = 0.f;

    for (int et = 0; et < 4; et++) {
        __syncthreads();
        #pragma unroll
        for (int k = 0; k < 4; k++) {
            int linear = k * 256 + t;
            int l = linear >> 2, esub = linear & 3;
            float4 xv = *(const float4*)&x[((size_t)(b * L + l)) * EXT + et * 16 + esub * 4];
            xsT[(esub * 4 + 0) * 264 + l] = xv.x;
            xsT[(esub * 4 + 1) * 264 + l] = xv.y;
            xsT[(esub * 4 + 2) * 264 + l] = xv.z;
            xsT[(esub * 4 + 3) * 264 + l] = xv.w;
        }
        __syncthreads();

        #pragma unroll
        for (int e = 0; e < 16; e++) {
            float4 xv = *(const float4*)&xsT[e * 264 + lq * 4];
            float4 wv = *(const float4*)&Ws[(et * 16 + e) * 16 + hq * 4];
            acc[0][0] = fmaf(xv.x, wv.x, acc[0][0]);
            acc[0][1] = fmaf(xv.x, wv.y, acc[0][1]);
            acc[0][2] = fmaf(xv.x, wv.z, acc[0][2]);
            acc[0][3] = fmaf(xv.x, wv.w, acc[0][3]);
            acc[1][0] = fmaf(xv.y, wv.x, acc[1][0]);
            acc[1][1] = fmaf(xv.y, wv.y, acc[1][1]);
            acc[1][2] = fmaf(xv.y, wv.z, acc[1][2]);
            acc[1][3] = fmaf(xv.y, wv.w, acc[1][3]);
            acc[2][0] = fmaf(xv.z, wv.x, acc[2][0]);
            acc[2][1] = fmaf(xv.z, wv.y, acc[2][1]);
            acc[2][2] = fmaf(xv.z, wv.z, acc[2][2]);
            acc[2][3] = fmaf(xv.z, wv.w, acc[2][3]);
            acc[3][0] = fmaf(xv.w, wv.x, acc[3][0]);
            acc[3][1] = fmaf(xv.w, wv.y, acc[3][1]);
            acc[3][2] = fmaf(xv.w, wv.z, acc[3][2]);
            acc[3][3] = fmaf(xv.w, wv.w, acc[3][3]);
        }
    }
    __syncthreads();

    #pragma unroll
    for (int j = 0; j < 4; j++) {
        int hh = hq * 4 + j;
        float cb = cbs[hh];
        float4 uv = make_float4(acc[0][j] + cb, acc[1][j] + cb,
                                acc[2][j] + cb, acc[3][j] + cb);
        *(float4*)&us[hh * 264 + lq * 4] = uv;
    }
    __syncthreads();

    int w = t >> 5, lane = t & 31;
    int sel = lane >> 4, p = lane & 15;
    int slot = w * 2 + sel;
    int h = hg * 16 + slot;

    float usum = 0.f;
    #pragma unroll
    for (int k = 0; k < 16; k++) usum += us[slot * 264 + p + 16 * k];
    usum = gredsum16(usum);

    int n0 = 2 * p;
    float dt = expf(log_dt[h]);
    float ar_s[2], ai_s[2], dAr_s[2], dAi_s[2];
    #pragma unroll
    for (int s = 0; s < 2; s++) {
        int idx = h * NST + n0 + s;
        ar_s[s] = -expf(logAr[idx]);
        ai_s[s] = Aim[idx];
        float er = expf(dt * ar_s[s]);
        dAr_s[s] = er * cosf(dt * ai_s[s]);
        dAi_s[s] = er * sinf(dt * ai_s[s]);
    }
    ull dAr2  = pack2(dAr_s[0], dAr_s[1]);
    ull dAi2  = pack2(dAi_s[0], dAi_s[1]);
    ull ndAi2 = pack2(-dAi_s[0], -dAi_s[1]);

    ull tr[4] = {0, 0, 0, 0}, ti[4] = {0, 0, 0, 0};
    #pragma unroll 4
    for (int j = 0; j < 64; j++) {
        #pragma unroll
        for (int c = 0; c < 4; c++) {
            float uv = us[slot * 264 + c * 64 + j];
            ull u2 = pack2(uv, uv);
            ull tA = f2fma(ndAi2, ti[c], u2);
            ull trn = f2fma(dAr2, tr[c], tA);
            ull tB = f2mul(dAr2, ti[c]);
            ti[c] = f2fma(dAi2, tr[c], tB);
            tr[c] = trn;
        }
    }

    float Trs[2], Tis[2];
    #pragma unroll
    for (int s = 0; s < 2; s++) {
        float e64 = expf(64.f * dt * ar_s[s]);
        float ang = 64.f * dt * ai_s[s];
        float Prr = e64 * cosf(ang), Pii = e64 * sinf(ang);
        float W2r = Prr, W2i = Pii;
        float W1r = Prr * Prr - Pii * Pii, W1i = 2.f * Prr * Pii;
        float W0r = W1r * Prr - W1i * Pii, W0i = W1i * Prr + W1r * Pii;
        float t3r, t3i, t2r, t2i, t1r, t1i, t0r, t0i, dum;
        if (s == 0) {
            unpack2(tr[3], t3r, dum); unpack2(ti[3], t3i, dum);
            unpack2(tr[2], t2r, dum); unpack2(ti[2], t2i, dum);
            unpack2(tr[1], t1r, dum); unpack2(ti[1], t1i, dum);
            unpack2(tr[0], t0r, dum); unpack2(ti[0], t0i, dum);
        } else {
            unpack2(tr[3], dum, t3r); unpack2(ti[3], dum, t3i);
            unpack2(tr[2], dum, t2r); unpack2(ti[2], dum, t2i);
            unpack2(tr[1], dum, t1r); unpack2(ti[1], dum, t1i);
            unpack2(tr[0], dum, t0r); unpack2(ti[0], dum, t0i);
        }
        Trs[s] = t3r + (W2r * t2r - W2i * t2i) + (W1r * t1r - W1i * t1i) + (W0r * t0r - W0i * t0i);
        Tis[s] = t3i + (W2i * t2r + W2r * t2i) + (W1i * t1r + W1r * t1i) + (W0i * t0r + W0r * t0i);
    }

    float val = 0.f;
    #pragma unroll
    for (int s = 0; s < 2; s++) {
        int idx = h * NST + n0 + s;
        float ar = ar_s[s], ai = ai_s[s];
        float dar = dAr_s[s], dai = dAi_s[s];
        float xr = dar * Trs[s] - dai * Tis[s];
        float xi = dai * Trs[s] + dar * Tis[s];
        float wr = usum - xr, wi = -xi;
        float den = ar * ar + ai * ai;
        float invr = -ar / den, invi = ai / den;
        float Sr = invr * wr - invi * wi;
        float Si = invr * wi + invi * wr;
        float s0r = sr0[b * H * NST + idx], s0i = si0[b * H * NST + idx];
        if (s0r != 0.f || s0i != 0.f) {
            float eL = expf((float)L * dt * ar);
            float phi = (float)L * dt * ai;
            float dALr = eL * cosf(phi), dALi = eL * sinf(phi);
            float numr = 1.f - dALr, numi = -dALi;
            float omr = 1.f - dar, omi = -dai;
            float r2 = omr * omr + omi * omi;
            float qr = (numr * omr + numi * omi) / r2;
            float qi = (numi * omr - numr * omi) / r2;
            float gr = dar * qr - dai * qi;
            float gi = dai * qr + dar * qi;
            Sr += gr * s0r - gi * s0i;
            Si += gr * s0i + gi * s0r;
        }
        val += Cre[idx] * Sr - Cim[idx] * Si;
    }
    val = gredsum16(val);
    if (p == 0)
        g_xm[b * H + h] = (2.f * val + (Dv[h] + 1.f) * usum) * (1.f / (float)L);
}

// ============ Kernel 2: head projections + per-batch consts ============
__global__ void k_heads(
    const float* __restrict__ writeW, const float* __restrict__ writeb,
    const float* __restrict__ readW,  const float* __restrict__ readb)
{
    __shared__ float xs[H];
    __shared__ float sow[3 * M + 6];
    __shared__ float sorh[M + 6];
    int b = blockIdx.x, t = threadIdx.x;
    if (t < H) xs[t] = g_xm[b * H + t];
    __syncthreads();

    if (t < 198) {
        float acc = writeb[t];
        for (int hh = 0; hh < H; hh++) acc = fmaf(xs[hh], writeW[hh * 198 + t], acc);
        sow[t] = acc;
    } else if (t < 268) {
        int j = t - 198;
        float acc = readb[j];
        for (int hh = 0; hh < H; hh++) acc = fmaf(xs[hh], readW[hh * 70 + j], acc);
        sorh[j] = acc;
    }
    __syncthreads();

    if (t < M) {
        g_kw[b * M + t] = sow[t];
        g_e[b * M + t]  = sigmoid_f(sow[M + 6 + t]);
        g_a[b * M + t]  = sow[2 * M + 6 + t];
        g_kr[b * M + t] = sorh[t];
    } else if (t == M) {
        float beta = softplus_f(sow[M]);
        float g    = sigmoid_f(sow[M + 1]);
        float m3 = fmaxf(sow[M + 2], fmaxf(sow[M + 3], sow[M + 4]));
        float e0 = expf(sow[M + 2] - m3), e1 = expf(sow[M + 3] - m3), e2 = expf(sow[M + 4] - m3);
        float Z = e0 + e1 + e2;
        float gamma = 1.f + softplus_f(sow[M + 5]);
        float nk = 0.f;
        for (int m = 0; m < M; m++) { float v = sow[m]; nk += v * v; }
        g_pw[b * 8 + 0] = beta; g_pw[b * 8 + 1] = g;
        g_pw[b * 8 + 2] = e0 / Z; g_pw[b * 8 + 3] = e1 / Z; g_pw[b * 8 + 4] = e2 / Z;
        g_pw[b * 8 + 5] = gamma; g_pw[b * 8 + 6] = sqrtf(nk);
    } else if (t == M + 1) {
        float beta = softplus_f(sorh[M]);
        float g    = sigmoid_f(sorh[M + 1]);
        float m3 = fmaxf(sorh[M + 2], fmaxf(sorh[M + 3], sorh[M + 4]));
        float e0 = expf(sorh[M + 2] - m3), e1 = expf(sorh[M + 3] - m3), e2 = expf(sorh[M + 4] - m3);
        float Z = e0 + e1 + e2;
        float gamma = 1.f + softplus_f(sorh[M + 5]);
        float nk = 0.f;
        for (int m = 0; m < M; m++) { float v = sorh[m]; nk += v * v; }
        g_pr[b * 8 + 0] = beta; g_pr[b * 8 + 1] = g;
        g_pr[b * 8 + 2] = e0 / Z; g_pr[b * 8 + 3] = e1 / Z; g_pr[b * 8 + 4] = e2 / Z;
        g_pr[b * 8 + 5] = gamma; g_pr[b * 8 + 6] = sqrtf(nk);
    } else if (t == M + 2) {
        float akr = 0.f, aa = 0.f;
        for (int m = 0; m < M; m++) {
            float av = sow[2 * M + 6 + m];
            akr = fmaf(av, sorh[m], akr);
            aa  = fmaf(av, av, aa);
        }
        g_pr[b * 8 + 7] = akr;
        g_pw[b * 8 + 7] = aa;
    }
}

// ============ Kernel 3: mem pass via smem column tiles; interleaved stat writes ============
__global__ void __launch_bounds__(256) k_pass1(const float* __restrict__ mem)
{
    __shared__ float tile[256 * 17];
    __shared__ float kw[M], kr_[M], ekr[M], ev[M], e2v[M], av[M], eav[M];
    int t = threadIdx.x;
    int b = blockIdx.x >> 4;
    int rowbase = blockIdx.x * 256;

    if (t < M) {
        float kwv = g_kw[b * M + t];
        float krv = g_kr[b * M + t];
        float e_  = g_e[b * M + t];
        float a_  = g_a[b * M + t];
        kw[t] = kwv; kr_[t] = krv; ekr[t] = e_ * krv;
        ev[t] = e_; e2v[t] = e_ * e_; av[t] = a_; eav[t] = e_ * a_;
    }

    float dw = 0.f, ss = 0.f, d1 = 0.f, d2 = 0.f, s2 = 0.f, s3 = 0.f, s4 = 0.f, s5 = 0.f;

    for (int ct = 0; ct < 4; ct++) {
        __syncthreads();
        #pragma unroll
        for (int k = 0; k < 4; k++) {
            int linear = k * 256 + t;
            int l = linear >> 2, f4 = linear & 3;
            float4 v = *(const float4*)(mem + (size_t)(rowbase + l) * M + ct * 16 + f4 * 4);
            tile[l * 17 + f4 * 4 + 0] = v.x;
            tile[l * 17 + f4 * 4 + 1] = v.y;
            tile[l * 17 + f4 * 4 + 2] = v.z;
            tile[l * 17 + f4 * 4 + 3] = v.w;
        }
        __syncthreads();

        #pragma unroll
        for (int c = 0; c < 16; c++) {
            float v = tile[t * 17 + c];
            int mm = ct * 16 + c;
            float v2 = v * v;
            dw = fmaf(v, kw[mm],  dw);
            ss += v2;
            d1 = fmaf(v, kr_[mm], d1);
            d2 = fmaf(v, ekr[mm], d2);
            s2 = fmaf(v2, ev[mm],  s2);
            s3 = fmaf(v2, e2v[mm], s3);
            s4 = fmaf(v, av[mm],  s4);
            s5 = fmaf(v, eav[mm], s5);
        }
    }

    int row = rowbase + t;
    float beta = g_pw[b * 8 + 0], knw = g_pw[b * 8 + 6];
    g_score[row] = beta * dw / (sqrtf(ss) * knw + 1e-16f);
    *(float4*)&g_st2[(size_t)row * 8]     = make_float4(d1, d2, ss, s2);
    *(float4*)&g_st2[(size_t)row * 8 + 4] = make_float4(s3, s4, s5, 0.f);
}

// ============ Kernel 4: addressing (scalar loops + float4 stats) ============
__global__ void __launch_bounds__(1024) k_addr2(
    const float* __restrict__ ww0, const float* __restrict__ wr0)
{
    __shared__ float sc[NMEM];
    __shared__ float wg[NMEM];
    __shared__ float red[32];
    __shared__ float bcast;
    int b = blockIdx.x, t = threadIdx.x;
    int lane = t & 31, w = t >> 5;

    // phase A: write addressing
    {
        float g = g_pw[b * 8 + 1], s0 = g_pw[b * 8 + 2], s1 = g_pw[b * 8 + 3];
        float s2 = g_pw[b * 8 + 4], gamma = g_pw[b * 8 + 5];

        float lm = __int_as_float(0xff800000);
        #pragma unroll
        for (int i = 0; i < 4; i++) {
            int n = t + 1024 * i;
            float v = g_score[b * NMEM + n];
            sc[n] = v; lm = fmaxf(lm, v);
        }
        lm = wredmax(lm);
        if (lane == 0) red[w] = lm;
        __syncthreads();
        if (w == 0) { float v = red[lane]; v = wredmax(v); if (lane == 0) bcast = v; }
        __syncthreads();
        float bm = bcast;

        float ls = 0.f;
        #pragma unroll
        for (int i = 0; i < 4; i++) {
            int n = t + 1024 * i;
            float pv = __expf(sc[n] - bm);
            sc[n] = pv; ls += pv;
        }
        ls = wredsum(ls);
        if (lane == 0) red[w] = ls;
        __syncthreads();
        if (w == 0) { float v = red[lane]; v = wredsum(v); if (lane == 0) bcast = v; }
        __syncthreads();
        float gZ = g / bcast, og = 1.f - g;

        #pragma unroll
        for (int i = 0; i < 4; i++) {
            int n = t + 1024 * i;
            wg[n] = fmaf(gZ, sc[n], og * ww0[b * NMEM + n]);
        }
        __syncthreads();

        float lp = 0.f;
        #pragma unroll
        for (int i = 0; i < 4; i++) {
            int n = t + 1024 * i;
            float wt = s0 * wg[(n - 1) & (NMEM - 1)] + s1 * wg[n] + s2 * wg[(n + 1) & (NMEM - 1)];
            float wp = (wt > 0.f) ? __powf(wt, gamma) : 0.f;
            sc[n] = wp; lp += wp;
        }
        lp = wredsum(lp);
        if (lane == 0) red[w] = lp;
        __syncthreads();
        if (w == 0) { float v = red[lane]; v = wredsum(v); if (lane == 0) bcast = v + 1e-16f; }
        __syncthreads();
        float iZp = 1.f / bcast;

        #pragma unroll
        for (int i = 0; i < 4; i++) {
            int n = t + 1024 * i;
            g_ww[b * NMEM + n] = sc[n] * iZp;
        }
        __syncthreads();
    }

    // phase B: read score from interleaved stats + read addressing
    {
        float beta = g_pr[b * 8 + 0], knr = g_pr[b * 8 + 6];
        float akr  = g_pr[b * 8 + 7], aa  = g_pw[b * 8 + 7];
        float g = g_pr[b * 8 + 1], s0 = g_pr[b * 8 + 2], s1 = g_pr[b * 8 + 3];
        float s2p = g_pr[b * 8 + 4], gamma = g_pr[b * 8 + 5];

        float lm = __int_as_float(0xff800000);
        #pragma unroll
        for (int i = 0; i < 4; i++) {
            int n = t + 1024 * i;
            int row = b * NMEM + n;
            float wwv = g_ww[row];
            float4 st0 = *(const float4*)&g_st2[(size_t)row * 8];
            float4 st1 = *(const float4*)&g_st2[(size_t)row * 8 + 4];
            float dot = st0.x - wwv * (st0.y - akr);
            float n2 = st0.z + wwv * (2.f * (st1.y - st0.w))
                     + wwv * wwv * (st1.x - 2.f * st1.z + aa);
            float v = beta * dot / (sqrtf(fmaxf(n2, 0.f)) * knr + 1e-16f);
            sc[n] = v; lm = fmaxf(lm, v);
        }
        lm = wredmax(lm);
        if (lane == 0) red[w] = lm;
        __syncthreads();
        if (w == 0) { float v = red[lane]; v = wredmax(v); if (lane == 0) bcast = v; }
        __syncthreads();
        float bm = bcast;

        float ls = 0.f;
        #pragma unroll
        for (int i = 0; i < 4; i++) {
            int n = t + 1024 * i;
            float pv = __expf(sc[n] - bm);
            sc[n] = pv; ls += pv;
        }
        ls = wredsum(ls);
        if (lane == 0) red[w] = ls;
        __syncthreads();
        if (w == 0) { float v = red[lane]; v = wredsum(v); if (lane == 0) bcast = v; }
        __syncthreads();
        float gZ = g / bcast, og = 1.f - g;

        #pragma unroll
        for (int i = 0; i < 4; i++) {
            int n = t + 1024 * i;
            wg[n] = fmaf(gZ, sc[n], og * wr0[b * NMEM + n]);
        }
        __syncthreads();

        float lp = 0.f;
        #pragma unroll
        for (int i = 0; i < 4; i++) {
            int n = t + 1024 * i;
            float wt = s0 * wg[(n - 1) & (NMEM - 1)] + s1 * wg[n] + s2p * wg[(n + 1) & (NMEM - 1)];
            float wp = (wt > 0.f) ? __powf(wt, gamma) : 0.f;
            sc[n] = wp; lp += wp;
        }
        lp = wredsum(lp);
        if (lane == 0) red[w] = lp;
        __syncthreads();
        if (w == 0) { float v = red[lane]; v = wredsum(v); if (lane == 0) bcast = v + 1e-16f; }
        __syncthreads();
        float iZp = 1.f / bcast;

        #pragma unroll
        for (int i = 0; i < 4; i++) {
            int n = t + 1024 * i;
            g_wr[b * NMEM + n] = sc[n] * iZp;
        }
    }
}

// ============ Kernel 5: r partials = w_r . mem2 + decoder tail ============
// grid (B, 32), block 256
__global__ void __launch_bounds__(256) k_readvec_dec(
    const float* __restrict__ mem, const float* __restrict__ decW,
    const float* __restrict__ decb, float* __restrict__ out)
{
    __shared__ float es4[M], as4[M];
    __shared__ float part[16][M + 4];
    __shared__ float xsd[H];
    __shared__ float rs[M];
    __shared__ int isLast;
    int b = blockIdx.x, chunk = blockIdx.y;
    int t = threadIdx.x;
    int m4 = t & 15;
    int rgrp = t >> 4;
    if (t < M) { es4[t] = g_e[b * M + t]; as4[t] = g_a[b * M + t]; }
    __syncthreads();

    int m = m4 * 4;
    float4 ev = make_float4(es4[m], es4[m + 1], es4[m + 2], es4[m + 3]);
    float4 av = make_float4(as4[m], as4[m + 1], as4[m + 2], as4[m + 3]);

    float4 acc = make_float4(0.f, 0.f, 0.f, 0.f);
    int n0 = chunk * 128;
    #pragma unroll
    for (int k = 0; k < 8; k++) {
        int n = n0 + rgrp + 16 * k;
        int row = b * NMEM + n;
        float wwv = g_ww[row], wrv = g_wr[row];
        float4 v = *(const float4*)(mem + (size_t)row * M + m);
        float4 v2;
        v2.x = fmaf(v.x, 1.f - wwv * ev.x, wwv * av.x);
        v2.y = fmaf(v.y, 1.f - wwv * ev.y, wwv * av.y);
        v2.z = fmaf(v.z, 1.f - wwv * ev.z, wwv * av.z);
        v2.w = fmaf(v.w, 1.f - wwv * ev.w, wwv * av.w);
        acc.x = fmaf(wrv, v2.x, acc.x);
        acc.y = fmaf(wrv, v2.y, acc.y);
        acc.z = fmaf(wrv, v2.z, acc.z);
        acc.w = fmaf(wrv, v2.w, acc.w);
    }
    *(float4*)&part[rgrp][m] = acc;
    __syncthreads();

    if (t < M) {
        float s = 0.f;
        #pragma unroll
        for (int r = 0; r < 16; r++) s += part[r][t];
        g_rpart[(b * 32 + chunk) * M + t] = s;
    }

    // ---- decoder tail: last chunk-block of this batch ----
    __threadfence();
    __syncthreads();
    if (t == 0) {
        int cpl = atomicAdd(&g_cntR[b], 1);
        isLast = (cpl == 31);
        if (cpl == 31) g_cntR[b] = 0;
    }
    __syncthreads();
    if (!isLast) return;
    __threadfence();

    xsd[t] = g_xm[b * H + t];
    if (t < M) {
        float s = 0.f;
        #pragma unroll
        for (int c = 0; c < 32; c++) s += g_rpart[(b * 32 + c) * M + t];
        rs[t] = s;
    }
    __syncthreads();
    if (t < OUT) {
        float acc2 = decb[t];
        for (int hh = 0; hh < H; hh++) acc2 = fmaf(xsd[hh], decW[hh * OUT + t], acc2);
        for (int mm = 0; mm < M; mm++) acc2 = fmaf(rs[mm], decW[(H + mm) * OUT + t], acc2);
        out[b * OUT + t] = acc2;
    }
}

// ---------------- launch ----------------
extern "C" void kernel_launch(void* const* d_in, const int* in_sizes, int n_in,
                              void* d_out, int out_size)
{
    const float* x      = (const float*)d_in[0];
    const float* r0     = (const float*)d_in[1];
    const float* sr0    = (const float*)d_in[2];
    const float* si0    = (const float*)d_in[3];
    const float* w_r0   = (const float*)d_in[4];
    const float* w_w0   = (const float*)d_in[5];
    const float* mem    = (const float*)d_in[6];
    const float* encW   = (const float*)d_in[7];
    const float* encb   = (const float*)d_in[8];
    const float* log_dt = (const float*)d_in[9];
    const float* logAr  = (const float*)d_in[10];
    const float* Aim    = (const float*)d_in[11];
    const float* Cre    = (const float*)d_in[12];
    const float* Cim    = (const float*)d_in[13];
    const float* Dv     = (const float*)d_in[14];
    const float* decW   = (const float*)d_in[15];
    const float* decb   = (const float*)d_in[16];
    const float* readW  = (const float*)d_in[17];
    const float* readb  = (const float*)d_in[18];
    const float* writeW = (const float*)d_in[19];
    const float* writeb = (const float*)d_in[20];
    float* out = (float*)d_out;

    k_encode_scan<<<dim3(B, H / 16), 256>>>(x, r0, sr0, si0, encW, encb,
                                            log_dt, logAr, Aim, Cre, Cim, Dv);
    k_heads<<<B, 288>>>(writeW, writeb, readW, readb);
    k_pass1<<<512, 256>>>(mem);
    k_addr2<<<B, 1024>>>(w_w0, w_r0);
    k_readvec_dec<<<dim3(B, 32), 256>>>(mem, decW, decb, out);
}

// round 16
// speedup vs baseline: 1.0817x; 1.0817x over previous
#include <cuda_runtime.h>
#include <math.h>

#define B 32
#define L 256
#define EXT 64
#define H 256
#define M 64
#define NMEM 4096
#define NST 32
#define OUT 64

typedef unsigned long long ull;

// ---------------- scratch (device globals; no allocation) ----------------
__device__ float g_xm[B * H];
__device__ float g_kw[B * M], g_e[B * M], g_a[B * M], g_kr[B * M];
__device__ float g_pw[B * 8], g_pr[B * 8];
__device__ float g_score[B * NMEM];
__device__ float g_st[7][B * NMEM];    // d1,d2,ss,s2,s3,s4,s5
__device__ float g_ww[B * NMEM], g_wr[B * NMEM];
__device__ float g_rpart[B * 32 * M];

// ---------------- helpers ----------------
__device__ __forceinline__ float wredsum(float v) {
    #pragma unroll
    for (int o = 16; o > 0; o >>= 1) v += __shfl_xor_sync(0xffffffffu, v, o);
    return v;
}
__device__ __forceinline__ float gredsum16(float v) {
    #pragma unroll
    for (int o = 8; o > 0; o >>= 1) v += __shfl_xor_sync(0xffffffffu, v, o);
    return v;
}
__device__ __forceinline__ float wredmax(float v) {
    #pragma unroll
    for (int o = 16; o > 0; o >>= 1) v = fmaxf(v, __shfl_xor_sync(0xffffffffu, v, o));
    return v;
}
__device__ __forceinline__ float softplus_f(float x) {
    return (x > 20.f) ? x : log1pf(expf(x));
}
__device__ __forceinline__ float sigmoid_f(float x) {
    return 1.f / (1.f + expf(-x));
}
__device__ __forceinline__ ull pack2(float lo, float hi) {
    ull r; asm("mov.b64 %0,{%1,%2};" : "=l"(r) : "f"(lo), "f"(hi)); return r;
}
__device__ __forceinline__ void unpack2(ull v, float& lo, float& hi) {
    asm("mov.b64 {%0,%1},%2;" : "=f"(lo), "=f"(hi) : "l"(v));
}
__device__ __forceinline__ ull f2fma(ull a, ull b, ull c) {
    ull d; asm("fma.rn.f32x2 %0,%1,%2,%3;" : "=l"(d) : "l"(a), "l"(b), "l"(c)); return d;
}

// ============ Kernel 1: register-tiled encoder GEMM + real 2nd-order scan ============
// grid (B, H/16), block 256.
// GEMM: thread = 4l x 4h tile. Scan: warp = 2 heads; 16-lane half packs 2 states/lane;
// 4-chunk ILP; real recurrence s_j = 2a*s_{j-1} - m*s_{j-2} + u_j (2 FMA2/step).
__global__ void __launch_bounds__(256) k_encode_scan(
    const float* __restrict__ x, const float* __restrict__ r0,
    const float* __restrict__ sr0, const float* __restrict__ si0,
    const float* __restrict__ encW, const float* __restrict__ encb,
    const float* __restrict__ log_dt, const float* __restrict__ logAr,
    const float* __restrict__ Aim, const float* __restrict__ Cre,
    const float* __restrict__ Cim, const float* __restrict__ Dv)
{
    __shared__ float Ws[64 * 16];
    __shared__ float cbs[16];
    __shared__ __align__(16) float xsT[16 * 264];
    __shared__ __align__(16) float us[16 * 264];

    int b = blockIdx.x, hg = blockIdx.y;
    int t = threadIdx.x;

    for (int i = t; i < 64 * 16; i += 256) {
        int e = i >> 4, hh = i & 15;
        Ws[i] = encW[e * H + hg * 16 + hh];
    }

    {
        int hh_b = t >> 4, p_b = t & 15;
        float cb = 0.f;
        #pragma unroll
        for (int m = p_b; m < M; m += 16)
            cb = fmaf(r0[b * M + m], encW[(EXT + m) * H + hg * 16 + hh_b], cb);
        cb = gredsum16(cb) + encb[hg * 16 + hh_b];
        if (p_b == 0) cbs[hh_b] = cb;
    }
    __syncthreads();

    int lq = t >> 2, hq = t & 3;
    float acc[4][4];
    #pragma unroll
    for (int i = 0; i < 4; i++)
        #pragma unroll
        for (int j = 0; j < 4; j++) acc[i][j] = 0.f;

    for (int et = 0; et < 4; et++) {
        __syncthreads();
        #pragma unroll
        for (int k = 0; k < 4; k++) {
            int linear = k * 256 + t;
            int l = linear >> 2, esub = linear & 3;
            float4 xv = *(const float4*)&x[((size_t)(b * L + l)) * EXT + et * 16 + esub * 4];
            xsT[(esub * 4 + 0) * 264 + l] = xv.x;
            xsT[(esub * 4 + 1) * 264 + l] = xv.y;
            xsT[(esub * 4 + 2) * 264 + l] = xv.z;
            xsT[(esub * 4 + 3) * 264 + l] = xv.w;
        }
        __syncthreads();

        #pragma unroll
        for (int e = 0; e < 16; e++) {
            float4 xv = *(const float4*)&xsT[e * 264 + lq * 4];
            float4 wv = *(const float4*)&Ws[(et * 16 + e) * 16 + hq * 4];
            acc[0][0] = fmaf(xv.x, wv.x, acc[0][0]);
            acc[0][1] = fmaf(xv.x, wv.y, acc[0][1]);
            acc[0][2] = fmaf(xv.x, wv.z, acc[0][2]);
            acc[0][3] = fmaf(xv.x, wv.w, acc[0][3]);
            acc[1][0] = fmaf(xv.y, wv.x, acc[1][0]);
            acc[1][1] = fmaf(xv.y, wv.y, acc[1][1]);
            acc[1][2] = fmaf(xv.y, wv.z, acc[1][2]);
            acc[1][3] = fmaf(xv.y, wv.w, acc[1][3]);
            acc[2][0] = fmaf(xv.z, wv.x, acc[2][0]);
            acc[2][1] = fmaf(xv.z, wv.y, acc[2][1]);
            acc[2][2] = fmaf(xv.z, wv.z, acc[2][2]);
            acc[2][3] = fmaf(xv.z, wv.w, acc[2][3]);
            acc[3][0] = fmaf(xv.w, wv.x, acc[3][0]);
            acc[3][1] = fmaf(xv.w, wv.y, acc[3][1]);
            acc[3][2] = fmaf(xv.w, wv.z, acc[3][2]);
            acc[3][3] = fmaf(xv.w, wv.w, acc[3][3]);
        }
    }
    __syncthreads();

    #pragma unroll
    for (int j = 0; j < 4; j++) {
        int hh = hq * 4 + j;
        float cb = cbs[hh];
        float4 uv = make_float4(acc[0][j] + cb, acc[1][j] + cb,
                                acc[2][j] + cb, acc[3][j] + cb);
        *(float4*)&us[hh * 264 + lq * 4] = uv;
    }
    __syncthreads();

    int w = t >> 5, lane = t & 31;
    int sel = lane >> 4, p = lane & 15;
    int slot = w * 2 + sel;
    int h = hg * 16 + slot;

    float usum = 0.f;
    #pragma unroll
    for (int k = 0; k < 16; k++) usum += us[slot * 264 + p + 16 * k];
    usum = gredsum16(usum);

    int n0 = 2 * p;
    float dt = expf(log_dt[h]);
    float ar_s[2], ai_s[2], dAr_s[2], dAi_s[2];
    #pragma unroll
    for (int s = 0; s < 2; s++) {
        int idx = h * NST + n0 + s;
        ar_s[s] = -expf(logAr[idx]);
        ai_s[s] = Aim[idx];
        float er = expf(dt * ar_s[s]);
        dAr_s[s] = er * cosf(dt * ai_s[s]);
        dAi_s[s] = er * sinf(dt * ai_s[s]);
    }
    // real 2nd-order recurrence constants: 2a and -m = -(a^2+b^2)
    float m_s0 = dAr_s[0] * dAr_s[0] + dAi_s[0] * dAi_s[0];
    float m_s1 = dAr_s[1] * dAr_s[1] + dAi_s[1] * dAi_s[1];
    ull twoA2 = pack2(2.f * dAr_s[0], 2.f * dAr_s[1]);
    ull negM2 = pack2(-m_s0, -m_s1);

    // scan: s_j = 2a*s_{j-1} - m*s_{j-2} + u_j, 4-chunk ILP
    ull scur[4] = {0, 0, 0, 0}, sprev[4] = {0, 0, 0, 0};
    #pragma unroll 4
    for (int j = 0; j < 64; j++) {
        #pragma unroll
        for (int c = 0; c < 4; c++) {
            float uv = us[slot * 264 + c * 64 + j];
            ull u2 = pack2(uv, uv);
            ull tmp = f2fma(negM2, sprev[c], u2);
            ull sn  = f2fma(twoA2, scur[c], tmp);
            sprev[c] = scur[c];
            scur[c]  = sn;
        }
    }

    // per chunk: T_c = (s63 - a*s62) + i*(b*s62); combine T = T3 + P*T2 + P^2*T1 + P^3*T0
    float Trs[2], Tis[2];
    #pragma unroll
    for (int s = 0; s < 2; s++) {
        float a = dAr_s[s], bb = dAi_s[s];
        float e64 = expf(64.f * dt * ar_s[s]);
        float ang = 64.f * dt * ai_s[s];
        float Prr = e64 * cosf(ang), Pii = e64 * sinf(ang);
        float W2r = Prr, W2i = Pii;
        float W1r = Prr * Prr - Pii * Pii, W1i = 2.f * Prr * Pii;
        float W0r = W1r * Prr - W1i * Pii, W0i = W1i * Prr + W1r * Pii;

        float tcr[4], tci[4];
        #pragma unroll
        for (int c = 0; c < 4; c++) {
            float s63a, s63b, s62a, s62b;
            unpack2(scur[c], s63a, s63b);
            unpack2(sprev[c], s62a, s62b);
            float s63 = (s == 0) ? s63a : s63b;
            float s62 = (s == 0) ? s62a : s62b;
            tcr[c] = s63 - a * s62;
            tci[c] = bb * s62;
        }
        Trs[s] = tcr[3] + (W2r * tcr[2] - W2i * tci[2])
               + (W1r * tcr[1] - W1i * tci[1]) + (W0r * tcr[0] - W0i * tci[0]);
        Tis[s] = tci[3] + (W2i * tcr[2] + W2r * tci[2])
               + (W1i * tcr[1] + W1r * tci[1]) + (W0i * tcr[0] + W0r * tci[0]);
    }

    // closed form: sum_l s_l = Geo*s0 + (-1/A)*(sum_u - dA*T)
    float val = 0.f;
    #pragma unroll
    for (int s = 0; s < 2; s++) {
        int idx = h * NST + n0 + s;
        float ar = ar_s[s], ai = ai_s[s];
        float dar = dAr_s[s], dai = dAi_s[s];
        float xr = dar * Trs[s] - dai * Tis[s];
        float xi = dai * Trs[s] + dar * Tis[s];
        float wr = usum - xr, wi = -xi;
        float den = ar * ar + ai * ai;
        float invr = -ar / den, invi = ai / den;
        float Sr = invr * wr - invi * wi;
        float Si = invr * wi + invi * wr;
        float s0r = sr0[b * H * NST + idx], s0i = si0[b * H * NST + idx];
        if (s0r != 0.f || s0i != 0.f) {
            float eL = expf((float)L * dt * ar);
            float phi = (float)L * dt * ai;
            float dALr = eL * cosf(phi), dALi = eL * sinf(phi);
            float numr = 1.f - dALr, numi = -dALi;
            float omr = 1.f - dar, omi = -dai;
            float r2 = omr * omr + omi * omi;
            float qr = (numr * omr + numi * omi) / r2;
            float qi = (numi * omr - numr * omi) / r2;
            float gr = dar * qr - dai * qi;
            float gi = dai * qr + dar * qi;
            Sr += gr * s0r - gi * s0i;
            Si += gr * s0i + gi * s0r;
        }
        val += Cre[idx] * Sr - Cim[idx] * Si;
    }
    val = gredsum16(val);
    if (p == 0)
        g_xm[b * H + h] = (2.f * val + (Dv[h] + 1.f) * usum) * (1.f / (float)L);
}

// ============ Kernel 2: head projections + per-batch consts ============
__global__ void k_heads(
    const float* __restrict__ writeW, const float* __restrict__ writeb,
    const float* __restrict__ readW,  const float* __restrict__ readb)
{
    __shared__ float xs[H];
    __shared__ float sow[3 * M + 6];
    __shared__ float sorh[M + 6];
    int b = blockIdx.x, t = threadIdx.x;
    if (t < H) xs[t] = g_xm[b * H + t];
    __syncthreads();

    if (t < 198) {
        float acc = writeb[t];
        for (int hh = 0; hh < H; hh++) acc = fmaf(xs[hh], writeW[hh * 198 + t], acc);
        sow[t] = acc;
    } else if (t < 268) {
        int j = t - 198;
        float acc = readb[j];
        for (int hh = 0; hh < H; hh++) acc = fmaf(xs[hh], readW[hh * 70 + j], acc);
        sorh[j] = acc;
    }
    __syncthreads();

    if (t < M) {
        g_kw[b * M + t] = sow[t];
        g_e[b * M + t]  = sigmoid_f(sow[M + 6 + t]);
        g_a[b * M + t]  = sow[2 * M + 6 + t];
        g_kr[b * M + t] = sorh[t];
    } else if (t == M) {
        float beta = softplus_f(sow[M]);
        float g    = sigmoid_f(sow[M + 1]);
        float m3 = fmaxf(sow[M + 2], fmaxf(sow[M + 3], sow[M + 4]));
        float e0 = expf(sow[M + 2] - m3), e1 = expf(sow[M + 3] - m3), e2 = expf(sow[M + 4] - m3);
        float Z = e0 + e1 + e2;
        float gamma = 1.f + softplus_f(sow[M + 5]);
        float nk = 0.f;
        for (int m = 0; m < M; m++) { float v = sow[m]; nk += v * v; }
        g_pw[b * 8 + 0] = beta; g_pw[b * 8 + 1] = g;
        g_pw[b * 8 + 2] = e0 / Z; g_pw[b * 8 + 3] = e1 / Z; g_pw[b * 8 + 4] = e2 / Z;
        g_pw[b * 8 + 5] = gamma; g_pw[b * 8 + 6] = sqrtf(nk);
    } else if (t == M + 1) {
        float beta = softplus_f(sorh[M]);
        float g    = sigmoid_f(sorh[M + 1]);
        float m3 = fmaxf(sorh[M + 2], fmaxf(sorh[M + 3], sorh[M + 4]));
        float e0 = expf(sorh[M + 2] - m3), e1 = expf(sorh[M + 3] - m3), e2 = expf(sorh[M + 4] - m3);
        float Z = e0 + e1 + e2;
        float gamma = 1.f + softplus_f(sorh[M + 5]);
        float nk = 0.f;
        for (int m = 0; m < M; m++) { float v = sorh[m]; nk += v * v; }
        g_pr[b * 8 + 0] = beta; g_pr[b * 8 + 1] = g;
        g_pr[b * 8 + 2] = e0 / Z; g_pr[b * 8 + 3] = e1 / Z; g_pr[b * 8 + 4] = e2 / Z;
        g_pr[b * 8 + 5] = gamma; g_pr[b * 8 + 6] = sqrtf(nk);
    } else if (t == M + 2) {
        float akr = 0.f, aa = 0.f;
        for (int m = 0; m < M; m++) {
            float av = sow[2 * M + 6 + m];
            akr = fmaf(av, sorh[m], akr);
            aa  = fmaf(av, av, aa);
        }
        g_pr[b * 8 + 7] = akr;
        g_pw[b * 8 + 7] = aa;
    }
}

// ============ Kernel 3: mem pass via smem column tiles ============
__global__ void __launch_bounds__(256) k_pass1(const float* __restrict__ mem)
{
    __shared__ float tile[256 * 17];
    __shared__ float kw[M], kr_[M], ekr[M], ev[M], e2v[M], av[M], eav[M];
    int t = threadIdx.x;
    int b = blockIdx.x >> 4;
    int rowbase = blockIdx.x * 256;

    if (t < M) {
        float kwv = g_kw[b * M + t];
        float krv = g_kr[b * M + t];
        float e_  = g_e[b * M + t];
        float a_  = g_a[b * M + t];
        kw[t] = kwv; kr_[t] = krv; ekr[t] = e_ * krv;
        ev[t] = e_; e2v[t] = e_ * e_; av[t] = a_; eav[t] = e_ * a_;
    }

    float dw = 0.f, ss = 0.f, d1 = 0.f, d2 = 0.f, s2 = 0.f, s3 = 0.f, s4 = 0.f, s5 = 0.f;

    for (int ct = 0; ct < 4; ct++) {
        __syncthreads();
        #pragma unroll
        for (int k = 0; k < 4; k++) {
            int linear = k * 256 + t;
            int l = linear >> 2, f4 = linear & 3;
            float4 v = *(const float4*)(mem + (size_t)(rowbase + l) * M + ct * 16 + f4 * 4);
            tile[l * 17 + f4 * 4 + 0] = v.x;
            tile[l * 17 + f4 * 4 + 1] = v.y;
            tile[l * 17 + f4 * 4 + 2] = v.z;
            tile[l * 17 + f4 * 4 + 3] = v.w;
        }
        __syncthreads();

        #pragma unroll
        for (int c = 0; c < 16; c++) {
            float v = tile[t * 17 + c];
            int mm = ct * 16 + c;
            float v2 = v * v;
            dw = fmaf(v, kw[mm],  dw);
            ss += v2;
            d1 = fmaf(v, kr_[mm], d1);
            d2 = fmaf(v, ekr[mm], d2);
            s2 = fmaf(v2, ev[mm],  s2);
            s3 = fmaf(v2, e2v[mm], s3);
            s4 = fmaf(v, av[mm],  s4);
            s5 = fmaf(v, eav[mm], s5);
        }
    }

    int row = rowbase + t;
    float beta = g_pw[b * 8 + 0], knw = g_pw[b * 8 + 6];
    g_score[row] = beta * dw / (sqrtf(ss) * knw + 1e-16f);
    g_st[0][row] = d1; g_st[1][row] = d2; g_st[2][row] = ss;
    g_st[3][row] = s2; g_st[4][row] = s3; g_st[5][row] = s4; g_st[6][row] = s5;
}

// ============ Kernel 4: write addressing + read score + read addressing ============
__global__ void __launch_bounds__(1024) k_addr2(
    const float* __restrict__ ww0, const float* __restrict__ wr0)
{
    __shared__ float sc[NMEM];
    __shared__ float wg[NMEM];
    __shared__ float red[32];
    __shared__ float bcast;
    int b = blockIdx.x, t = threadIdx.x;
    int lane = t & 31, w = t >> 5;

    // phase A: write addressing
    {
        float g = g_pw[b * 8 + 1], s0 = g_pw[b * 8 + 2], s1 = g_pw[b * 8 + 3];
        float s2 = g_pw[b * 8 + 4], gamma = g_pw[b * 8 + 5];

        float lm = __int_as_float(0xff800000);
        #pragma unroll
        for (int i = 0; i < 4; i++) {
            int n = t + 1024 * i;
            float v = g_score[b * NMEM + n];
            sc[n] = v; lm = fmaxf(lm, v);
        }
        lm = wredmax(lm);
        if (lane == 0) red[w] = lm;
        __syncthreads();
        if (w == 0) { float v = red[lane]; v = wredmax(v); if (lane == 0) bcast = v; }
        __syncthreads();
        float bm = bcast;

        float ls = 0.f;
        #pragma unroll
        for (int i = 0; i < 4; i++) {
            int n = t + 1024 * i;
            float pv = __expf(sc[n] - bm);
            sc[n] = pv; ls += pv;
        }
        ls = wredsum(ls);
        if (lane == 0) red[w] = ls;
        __syncthreads();
        if (w == 0) { float v = red[lane]; v = wredsum(v); if (lane == 0) bcast = v; }
        __syncthreads();
        float gZ = g / bcast, og = 1.f - g;

        #pragma unroll
        for (int i = 0; i < 4; i++) {
            int n = t + 1024 * i;
            wg[n] = fmaf(gZ, sc[n], og * ww0[b * NMEM + n]);
        }
        __syncthreads();

        float lp = 0.f;
        #pragma unroll
        for (int i = 0; i < 4; i++) {
            int n = t + 1024 * i;
            float wt = s0 * wg[(n - 1) & (NMEM - 1)] + s1 * wg[n] + s2 * wg[(n + 1) & (NMEM - 1)];
            float wp = (wt > 0.f) ? __powf(wt, gamma) : 0.f;
            sc[n] = wp; lp += wp;
        }
        lp = wredsum(lp);
        if (lane == 0) red[w] = lp;
        __syncthreads();
        if (w == 0) { float v = red[lane]; v = wredsum(v); if (lane == 0) bcast = v + 1e-16f; }
        __syncthreads();
        float iZp = 1.f / bcast;

        #pragma unroll
        for (int i = 0; i < 4; i++) {
            int n = t + 1024 * i;
            g_ww[b * NMEM + n] = sc[n] * iZp;
        }
        __syncthreads();
    }

    // phase B: read score from stats + read addressing
    {
        float beta = g_pr[b * 8 + 0], knr = g_pr[b * 8 + 6];
        float akr  = g_pr[b * 8 + 7], aa  = g_pw[b * 8 + 7];
        float g = g_pr[b * 8 + 1], s0 = g_pr[b * 8 + 2], s1 = g_pr[b * 8 + 3];
        float s2p = g_pr[b * 8 + 4], gamma = g_pr[b * 8 + 5];

        float lm = __int_as_float(0xff800000);
        #pragma unroll
        for (int i = 0; i < 4; i++) {
            int n = t + 1024 * i;
            int row = b * NMEM + n;
            float wwv = g_ww[row];
            float d1 = g_st[0][row], d2 = g_st[1][row], ssv = g_st[2][row];
            float s2v = g_st[3][row], s3v = g_st[4][row], s4v = g_st[5][row], s5v = g_st[6][row];
            float dot = d1 - wwv * (d2 - akr);
            float n2 = ssv + wwv * (2.f * (s4v - s2v)) + wwv * wwv * (s3v - 2.f * s5v + aa);
            float v = beta * dot / (sqrtf(fmaxf(n2, 0.f)) * knr + 1e-16f);
            sc[n] = v; lm = fmaxf(lm, v);
        }
        lm = wredmax(lm);
        if (lane == 0) red[w] = lm;
        __syncthreads();
        if (w == 0) { float v = red[lane]; v = wredmax(v); if (lane == 0) bcast = v; }
        __syncthreads();
        float bm = bcast;

        float ls = 0.f;
        #pragma unroll
        for (int i = 0; i < 4; i++) {
            int n = t + 1024 * i;
            float pv = __expf(sc[n] - bm);
            sc[n] = pv; ls += pv;
        }
        ls = wredsum(ls);
        if (lane == 0) red[w] = ls;
        __syncthreads();
        if (w == 0) { float v = red[lane]; v = wredsum(v); if (lane == 0) bcast = v; }
        __syncthreads();
        float gZ = g / bcast, og = 1.f - g;

        #pragma unroll
        for (int i = 0; i < 4; i++) {
            int n = t + 1024 * i;
            wg[n] = fmaf(gZ, sc[n], og * wr0[b * NMEM + n]);
        }
        __syncthreads();

        float lp = 0.f;
        #pragma unroll
        for (int i = 0; i < 4; i++) {
            int n = t + 1024 * i;
            float wt = s0 * wg[(n - 1) & (NMEM - 1)] + s1 * wg[n] + s2p * wg[(n + 1) & (NMEM - 1)];
            float wp = (wt > 0.f) ? __powf(wt, gamma) : 0.f;
            sc[n] = wp; lp += wp;
        }
        lp = wredsum(lp);
        if (lane == 0) red[w] = lp;
        __syncthreads();
        if (w == 0) { float v = red[lane]; v = wredsum(v); if (lane == 0) bcast = v + 1e-16f; }
        __syncthreads();
        float iZp = 1.f / bcast;

        #pragma unroll
        for (int i = 0; i < 4; i++) {
            int n = t + 1024 * i;
            g_wr[b * NMEM + n] = sc[n] * iZp;
        }
    }
}

// ============ Kernel 5: r partials = w_r . mem2 ============
__global__ void __launch_bounds__(256) k_readvec(const float* __restrict__ mem)
{
    __shared__ float es4[M], as4[M];
    __shared__ float part[16][M + 4];
    int b = blockIdx.x, chunk = blockIdx.y;
    int t = threadIdx.x;
    int m4 = t & 15;
    int rgrp = t >> 4;
    if (t < M) { es4[t] = g_e[b * M + t]; as4[t] = g_a[b * M + t]; }
    __syncthreads();

    int m = m4 * 4;
    float4 ev = make_float4(es4[m], es4[m + 1], es4[m + 2], es4[m + 3]);
    float4 av = make_float4(as4[m], as4[m + 1], as4[m + 2], as4[m + 3]);

    float4 acc = make_float4(0.f, 0.f, 0.f, 0.f);
    int n0 = chunk * 128;
    #pragma unroll
    for (int k = 0; k < 8; k++) {
        int n = n0 + rgrp + 16 * k;
        int row = b * NMEM + n;
        float wwv = g_ww[row], wrv = g_wr[row];
        float4 v = *(const float4*)(mem + (size_t)row * M + m);
        float4 v2;
        v2.x = fmaf(v.x, 1.f - wwv * ev.x, wwv * av.x);
        v2.y = fmaf(v.y, 1.f - wwv * ev.y, wwv * av.y);
        v2.z = fmaf(v.z, 1.f - wwv * ev.z, wwv * av.z);
        v2.w = fmaf(v.w, 1.f - wwv * ev.w, wwv * av.w);
        acc.x = fmaf(wrv, v2.x, acc.x);
        acc.y = fmaf(wrv, v2.y, acc.y);
        acc.z = fmaf(wrv, v2.z, acc.z);
        acc.w = fmaf(wrv, v2.w, acc.w);
    }
    *(float4*)&part[rgrp][m] = acc;
    __syncthreads();

    if (t < M) {
        float s = 0.f;
        #pragma unroll
        for (int r = 0; r < 16; r++) s += part[r][t];
        g_rpart[(b * 32 + chunk) * M + t] = s;
    }
}

// ============ Kernel 6: decoder ============
__global__ void k_decode(const float* __restrict__ decW, const float* __restrict__ decb,
                         float* __restrict__ out)
{
    __shared__ float xs[H];
    __shared__ float rs[M];
    int b = blockIdx.x, t = threadIdx.x;
    xs[t] = g_xm[b * H + t];
    if (t < M) {
        float s = 0.f;
        #pragma unroll
        for (int c = 0; c < 32; c++) s += g_rpart[(b * 32 + c) * M + t];
        rs[t] = s;
    }
    __syncthreads();
    if (t < OUT) {
        float acc = decb[t];
        for (int hh = 0; hh < H; hh++) acc = fmaf(xs[hh], decW[hh * OUT + t], acc);
        for (int m = 0; m < M; m++) acc = fmaf(rs[m], decW[(H + m) * OUT + t], acc);
        out[b * OUT + t] = acc;
    }
}

// ---------------- launch ----------------
extern "C" void kernel_launch(void* const* d_in, const int* in_sizes, int n_in,
                              void* d_out, int out_size)
{
    const float* x      = (const float*)d_in[0];
    const float* r0     = (const float*)d_in[1];
    const float* sr0    = (const float*)d_in[2];
    const float* si0    = (const float*)d_in[3];
    const float* w_r0   = (const float*)d_in[4];
    const float* w_w0   = (const float*)d_in[5];
    const float* mem    = (const float*)d_in[6];
    const float* encW   = (const float*)d_in[7];
    const float* encb   = (const float*)d_in[8];
    const float* log_dt = (const float*)d_in[9];
    const float* logAr  = (const float*)d_in[10];
    const float* Aim    = (const float*)d_in[11];
    const float* Cre    = (const float*)d_in[12];
    const float* Cim    = (const float*)d_in[13];
    const float* Dv     = (const float*)d_in[14];
    const float* decW   = (const float*)d_in[15];
    const float* decb   = (const float*)d_in[16];
    const float* readW  = (const float*)d_in[17];
    const float* readb  = (const float*)d_in[18];
    const float* writeW = (const float*)d_in[19];
    const float* writeb = (const float*)d_in[20];
    float* out = (float*)d_out;

    k_encode_scan<<<dim3(B, H / 16), 256>>>(x, r0, sr0, si0, encW, encb,
                                            log_dt, logAr, Aim, Cre, Cim, Dv);
    k_heads<<<B, 288>>>(writeW, writeb, readW, readb);
    k_pass1<<<512, 256>>>(mem);
    k_addr2<<<B, 1024>>>(w_w0, w_r0);
    k_readvec<<<dim3(B, 32), 256>>>(mem);
    k_decode<<<B, 256>>>(decW, decb, out);
}

// round 17
// speedup vs baseline: 1.0972x; 1.0143x over previous
#include <cuda_runtime.h>
#include <math.h>

#define B 32
#define L 256
#define EXT 64
#define H 256
#define M 64
#define NMEM 4096
#define NST 32
#define OUT 64

typedef unsigned long long ull;

// ---------------- scratch (device globals; no allocation) ----------------
__device__ float g_xm[B * H];
__device__ float g_kw[B * M], g_e[B * M], g_a[B * M], g_kr[B * M];
__device__ float g_pw[B * 8], g_pr[B * 8];
__device__ float g_score[B * NMEM];
__device__ float g_st[7][B * NMEM];    // d1,d2,ss,s2,s3,s4,s5
__device__ float g_ww[B * NMEM], g_wr[B * NMEM];
__device__ float g_rpart[B * 32 * M];

// ---------------- helpers ----------------
__device__ __forceinline__ float wredsum(float v) {
    #pragma unroll
    for (int o = 16; o > 0; o >>= 1) v += __shfl_xor_sync(0xffffffffu, v, o);
    return v;
}
__device__ __forceinline__ float gredsum16(float v) {
    #pragma unroll
    for (int o = 8; o > 0; o >>= 1) v += __shfl_xor_sync(0xffffffffu, v, o);
    return v;
}
__device__ __forceinline__ float wredmax(float v) {
    #pragma unroll
    for (int o = 16; o > 0; o >>= 1) v = fmaxf(v, __shfl_xor_sync(0xffffffffu, v, o));
    return v;
}
__device__ __forceinline__ float softplus_f(float x) {
    return (x > 20.f) ? x : log1pf(expf(x));
}
__device__ __forceinline__ float sigmoid_f(float x) {
    return 1.f / (1.f + expf(-x));
}
__device__ __forceinline__ ull pack2(float lo, float hi) {
    ull r; asm("mov.b64 %0,{%1,%2};" : "=l"(r) : "f"(lo), "f"(hi)); return r;
}
__device__ __forceinline__ void unpack2(ull v, float& lo, float& hi) {
    asm("mov.b64 {%0,%1},%2;" : "=f"(lo), "=f"(hi) : "l"(v));
}
__device__ __forceinline__ ull f2fma(ull a, ull b, ull c) {
    ull d; asm("fma.rn.f32x2 %0,%1,%2,%3;" : "=l"(d) : "l"(a), "l"(b), "l"(c)); return d;
}

// ============ Kernel 1: register-tiled encoder GEMM + real 2nd-order scan ============
__global__ void __launch_bounds__(256) k_encode_scan(
    const float* __restrict__ x, const float* __restrict__ r0,
    const float* __restrict__ sr0, const float* __restrict__ si0,
    const float* __restrict__ encW, const float* __restrict__ encb,
    const float* __restrict__ log_dt, const float* __restrict__ logAr,
    const float* __restrict__ Aim, const float* __restrict__ Cre,
    const float* __restrict__ Cim, const float* __restrict__ Dv)
{
    __shared__ float Ws[64 * 16];
    __shared__ float cbs[16];
    __shared__ __align__(16) float xsT[16 * 264];
    __shared__ __align__(16) float us[16 * 264];

    int b = blockIdx.x, hg = blockIdx.y;
    int t = threadIdx.x;

    for (int i = t; i < 64 * 16; i += 256) {
        int e = i >> 4, hh = i & 15;
        Ws[i] = encW[e * H + hg * 16 + hh];
    }

    {
        int hh_b = t >> 4, p_b = t & 15;
        float cb = 0.f;
        #pragma unroll
        for (int m = p_b; m < M; m += 16)
            cb = fmaf(r0[b * M + m], encW[(EXT + m) * H + hg * 16 + hh_b], cb);
        cb = gredsum16(cb) + encb[hg * 16 + hh_b];
        if (p_b == 0) cbs[hh_b] = cb;
    }
    __syncthreads();

    int lq = t >> 2, hq = t & 3;
    float acc[4][4];
    #pragma unroll
    for (int i = 0; i < 4; i++)
        #pragma unroll
        for (int j = 0; j < 4; j++) acc[i][j] = 0.f;

    for (int et = 0; et < 4; et++) {
        __syncthreads();
        #pragma unroll
        for (int k = 0; k < 4; k++) {
            int linear = k * 256 + t;
            int l = linear >> 2, esub = linear & 3;
            float4 xv = *(const float4*)&x[((size_t)(b * L + l)) * EXT + et * 16 + esub * 4];
            xsT[(esub * 4 + 0) * 264 + l] = xv.x;
            xsT[(esub * 4 + 1) * 264 + l] = xv.y;
            xsT[(esub * 4 + 2) * 264 + l] = xv.z;
            xsT[(esub * 4 + 3) * 264 + l] = xv.w;
        }
        __syncthreads();

        #pragma unroll
        for (int e = 0; e < 16; e++) {
            float4 xv = *(const float4*)&xsT[e * 264 + lq * 4];
            float4 wv = *(const float4*)&Ws[(et * 16 + e) * 16 + hq * 4];
            acc[0][0] = fmaf(xv.x, wv.x, acc[0][0]);
            acc[0][1] = fmaf(xv.x, wv.y, acc[0][1]);
            acc[0][2] = fmaf(xv.x, wv.z, acc[0][2]);
            acc[0][3] = fmaf(xv.x, wv.w, acc[0][3]);
            acc[1][0] = fmaf(xv.y, wv.x, acc[1][0]);
            acc[1][1] = fmaf(xv.y, wv.y, acc[1][1]);
            acc[1][2] = fmaf(xv.y, wv.z, acc[1][2]);
            acc[1][3] = fmaf(xv.y, wv.w, acc[1][3]);
            acc[2][0] = fmaf(xv.z, wv.x, acc[2][0]);
            acc[2][1] = fmaf(xv.z, wv.y, acc[2][1]);
            acc[2][2] = fmaf(xv.z, wv.z, acc[2][2]);
            acc[2][3] = fmaf(xv.z, wv.w, acc[2][3]);
            acc[3][0] = fmaf(xv.w, wv.x, acc[3][0]);
            acc[3][1] = fmaf(xv.w, wv.y, acc[3][1]);
            acc[3][2] = fmaf(xv.w, wv.z, acc[3][2]);
            acc[3][3] = fmaf(xv.w, wv.w, acc[3][3]);
        }
    }
    __syncthreads();

    #pragma unroll
    for (int j = 0; j < 4; j++) {
        int hh = hq * 4 + j;
        float cb = cbs[hh];
        float4 uv = make_float4(acc[0][j] + cb, acc[1][j] + cb,
                                acc[2][j] + cb, acc[3][j] + cb);
        *(float4*)&us[hh * 264 + lq * 4] = uv;
    }
    __syncthreads();

    int w = t >> 5, lane = t & 31;
    int sel = lane >> 4, p = lane & 15;
    int slot = w * 2 + sel;
    int h = hg * 16 + slot;

    float usum = 0.f;
    #pragma unroll
    for (int k = 0; k < 16; k++) usum += us[slot * 264 + p + 16 * k];
    usum = gredsum16(usum);

    int n0 = 2 * p;
    float dt = expf(log_dt[h]);
    float ar_s[2], ai_s[2], dAr_s[2], dAi_s[2];
    #pragma unroll
    for (int s = 0; s < 2; s++) {
        int idx = h * NST + n0 + s;
        ar_s[s] = -expf(logAr[idx]);
        ai_s[s] = Aim[idx];
        float er = expf(dt * ar_s[s]);
        dAr_s[s] = er * cosf(dt * ai_s[s]);
        dAi_s[s] = er * sinf(dt * ai_s[s]);
    }
    float m_s0 = dAr_s[0] * dAr_s[0] + dAi_s[0] * dAi_s[0];
    float m_s1 = dAr_s[1] * dAr_s[1] + dAi_s[1] * dAi_s[1];
    ull twoA2 = pack2(2.f * dAr_s[0], 2.f * dAr_s[1]);
    ull negM2 = pack2(-m_s0, -m_s1);

    ull scur[4] = {0, 0, 0, 0}, sprev[4] = {0, 0, 0, 0};
    #pragma unroll 4
    for (int j = 0; j < 64; j++) {
        #pragma unroll
        for (int c = 0; c < 4; c++) {
            float uv = us[slot * 264 + c * 64 + j];
            ull u2 = pack2(uv, uv);
            ull tmp = f2fma(negM2, sprev[c], u2);
            ull sn  = f2fma(twoA2, scur[c], tmp);
            sprev[c] = scur[c];
            scur[c]  = sn;
        }
    }

    float Trs[2], Tis[2];
    #pragma unroll
    for (int s = 0; s < 2; s++) {
        float a = dAr_s[s], bb = dAi_s[s];
        float e64 = expf(64.f * dt * ar_s[s]);
        float ang = 64.f * dt * ai_s[s];
        float Prr = e64 * cosf(ang), Pii = e64 * sinf(ang);
        float W2r = Prr, W2i = Pii;
        float W1r = Prr * Prr - Pii * Pii, W1i = 2.f * Prr * Pii;
        float W0r = W1r * Prr - W1i * Pii, W0i = W1i * Prr + W1r * Pii;

        float tcr[4], tci[4];
        #pragma unroll
        for (int c = 0; c < 4; c++) {
            float s63a, s63b, s62a, s62b;
            unpack2(scur[c], s63a, s63b);
            unpack2(sprev[c], s62a, s62b);
            float s63 = (s == 0) ? s63a : s63b;
            float s62 = (s == 0) ? s62a : s62b;
            tcr[c] = s63 - a * s62;
            tci[c] = bb * s62;
        }
        Trs[s] = tcr[3] + (W2r * tcr[2] - W2i * tci[2])
               + (W1r * tcr[1] - W1i * tci[1]) + (W0r * tcr[0] - W0i * tci[0]);
        Tis[s] = tci[3] + (W2i * tcr[2] + W2r * tci[2])
               + (W1i * tcr[1] + W1r * tci[1]) + (W0i * tcr[0] + W0r * tci[0]);
    }

    float val = 0.f;
    #pragma unroll
    for (int s = 0; s < 2; s++) {
        int idx = h * NST + n0 + s;
        float ar = ar_s[s], ai = ai_s[s];
        float dar = dAr_s[s], dai = dAi_s[s];
        float xr = dar * Trs[s] - dai * Tis[s];
        float xi = dai * Trs[s] + dar * Tis[s];
        float wr = usum - xr, wi = -xi;
        float den = ar * ar + ai * ai;
        float invr = -ar / den, invi = ai / den;
        float Sr = invr * wr - invi * wi;
        float Si = invr * wi + invi * wr;
        float s0r = sr0[b * H * NST + idx], s0i = si0[b * H * NST + idx];
        if (s0r != 0.f || s0i != 0.f) {
            float eL = expf((float)L * dt * ar);
            float phi = (float)L * dt * ai;
            float dALr = eL * cosf(phi), dALi = eL * sinf(phi);
            float numr = 1.f - dALr, numi = -dALi;
            float omr = 1.f - dar, omi = -dai;
            float r2 = omr * omr + omi * omi;
            float qr = (numr * omr + numi * omi) / r2;
            float qi = (numi * omr - numr * omi) / r2;
            float gr = dar * qr - dai * qi;
            float gi = dai * qr + dar * qi;
            Sr += gr * s0r - gi * s0i;
            Si += gr * s0i + gi * s0r;
        }
        val += Cre[idx] * Sr - Cim[idx] * Si;
    }
    val = gredsum16(val);
    if (p == 0)
        g_xm[b * H + h] = (2.f * val + (Dv[h] + 1.f) * usum) * (1.f / (float)L);
}

// ============ Kernel 2: head projections + per-batch consts ============
__global__ void k_heads(
    const float* __restrict__ writeW, const float* __restrict__ writeb,
    const float* __restrict__ readW,  const float* __restrict__ readb)
{
    __shared__ float xs[H];
    __shared__ float sow[3 * M + 6];
    __shared__ float sorh[M + 6];
    int b = blockIdx.x, t = threadIdx.x;
    if (t < H) xs[t] = g_xm[b * H + t];
    __syncthreads();

    if (t < 198) {
        float acc = writeb[t];
        for (int hh = 0; hh < H; hh++) acc = fmaf(xs[hh], writeW[hh * 198 + t], acc);
        sow[t] = acc;
    } else if (t < 268) {
        int j = t - 198;
        float acc = readb[j];
        for (int hh = 0; hh < H; hh++) acc = fmaf(xs[hh], readW[hh * 70 + j], acc);
        sorh[j] = acc;
    }
    __syncthreads();

    if (t < M) {
        g_kw[b * M + t] = sow[t];
        g_e[b * M + t]  = sigmoid_f(sow[M + 6 + t]);
        g_a[b * M + t]  = sow[2 * M + 6 + t];
        g_kr[b * M + t] = sorh[t];
    } else if (t == M) {
        float beta = softplus_f(sow[M]);
        float g    = sigmoid_f(sow[M + 1]);
        float m3 = fmaxf(sow[M + 2], fmaxf(sow[M + 3], sow[M + 4]));
        float e0 = expf(sow[M + 2] - m3), e1 = expf(sow[M + 3] - m3), e2 = expf(sow[M + 4] - m3);
        float Z = e0 + e1 + e2;
        float gamma = 1.f + softplus_f(sow[M + 5]);
        float nk = 0.f;
        for (int m = 0; m < M; m++) { float v = sow[m]; nk += v * v; }
        g_pw[b * 8 + 0] = beta; g_pw[b * 8 + 1] = g;
        g_pw[b * 8 + 2] = e0 / Z; g_pw[b * 8 + 3] = e1 / Z; g_pw[b * 8 + 4] = e2 / Z;
        g_pw[b * 8 + 5] = gamma; g_pw[b * 8 + 6] = sqrtf(nk);
    } else if (t == M + 1) {
        float beta = softplus_f(sorh[M]);
        float g    = sigmoid_f(sorh[M + 1]);
        float m3 = fmaxf(sorh[M + 2], fmaxf(sorh[M + 3], sorh[M + 4]));
        float e0 = expf(sorh[M + 2] - m3), e1 = expf(sorh[M + 3] - m3), e2 = expf(sorh[M + 4] - m3);
        float Z = e0 + e1 + e2;
        float gamma = 1.f + softplus_f(sorh[M + 5]);
        float nk = 0.f;
        for (int m = 0; m < M; m++) { float v = sorh[m]; nk += v * v; }
        g_pr[b * 8 + 0] = beta; g_pr[b * 8 + 1] = g;
        g_pr[b * 8 + 2] = e0 / Z; g_pr[b * 8 + 3] = e1 / Z; g_pr[b * 8 + 4] = e2 / Z;
        g_pr[b * 8 + 5] = gamma; g_pr[b * 8 + 6] = sqrtf(nk);
    } else if (t == M + 2) {
        float akr = 0.f, aa = 0.f;
        for (int m = 0; m < M; m++) {
            float av = sow[2 * M + 6 + m];
            akr = fmaf(av, sorh[m], akr);
            aa  = fmaf(av, av, aa);
        }
        g_pr[b * 8 + 7] = akr;
        g_pw[b * 8 + 7] = aa;
    }
}

// ============ Kernel 3: mem pass via smem column tiles ============
__global__ void __launch_bounds__(256) k_pass1(const float* __restrict__ mem)
{
    __shared__ float tile[256 * 17];
    __shared__ float kw[M], kr_[M], ekr[M], ev[M], e2v[M], av[M], eav[M];
    int t = threadIdx.x;
    int b = blockIdx.x >> 4;
    int rowbase = blockIdx.x * 256;

    if (t < M) {
        float kwv = g_kw[b * M + t];
        float krv = g_kr[b * M + t];
        float e_  = g_e[b * M + t];
        float a_  = g_a[b * M + t];
        kw[t] = kwv; kr_[t] = krv; ekr[t] = e_ * krv;
        ev[t] = e_; e2v[t] = e_ * e_; av[t] = a_; eav[t] = e_ * a_;
    }

    float dw = 0.f, ss = 0.f, d1 = 0.f, d2 = 0.f, s2 = 0.f, s3 = 0.f, s4 = 0.f, s5 = 0.f;

    for (int ct = 0; ct < 4; ct++) {
        __syncthreads();
        #pragma unroll
        for (int k = 0; k < 4; k++) {
            int linear = k * 256 + t;
            int l = linear >> 2, f4 = linear & 3;
            float4 v = *(const float4*)(mem + (size_t)(rowbase + l) * M + ct * 16 + f4 * 4);
            tile[l * 17 + f4 * 4 + 0] = v.x;
            tile[l * 17 + f4 * 4 + 1] = v.y;
            tile[l * 17 + f4 * 4 + 2] = v.z;
            tile[l * 17 + f4 * 4 + 3] = v.w;
        }
        __syncthreads();

        #pragma unroll
        for (int c = 0; c < 16; c++) {
            float v = tile[t * 17 + c];
            int mm = ct * 16 + c;
            float v2 = v * v;
            dw = fmaf(v, kw[mm],  dw);
            ss += v2;
            d1 = fmaf(v, kr_[mm], d1);
            d2 = fmaf(v, ekr[mm], d2);
            s2 = fmaf(v2, ev[mm],  s2);
            s3 = fmaf(v2, e2v[mm], s3);
            s4 = fmaf(v, av[mm],  s4);
            s5 = fmaf(v, eav[mm], s5);
        }
    }

    int row = rowbase + t;
    float beta = g_pw[b * 8 + 0], knw = g_pw[b * 8 + 6];
    g_score[row] = beta * dw / (sqrtf(ss) * knw + 1e-16f);
    g_st[0][row] = d1; g_st[1][row] = d2; g_st[2][row] = ss;
    g_st[3][row] = s2; g_st[4][row] = s3; g_st[5][row] = s4; g_st[6][row] = s5;
}

// ============ Kernel 4: addressing with stat prefetch + register-carried w_w ============
__global__ void __launch_bounds__(1024) k_addr2(
    const float* __restrict__ ww0, const float* __restrict__ wr0)
{
    __shared__ float sc[NMEM];
    __shared__ float wg[NMEM];
    __shared__ float red[32];
    __shared__ float bcast;
    int b = blockIdx.x, t = threadIdx.x;
    int lane = t & 31, w = t >> 5;

    // prefetch phase-B stats NOW — latency hides behind all of phase A
    float pd1[4], pd2[4], pss[4], ps2[4], ps3[4], ps4[4], ps5[4];
    #pragma unroll
    for (int i = 0; i < 4; i++) {
        int row = b * NMEM + t + 1024 * i;
        pd1[i] = g_st[0][row]; pd2[i] = g_st[1][row]; pss[i] = g_st[2][row];
        ps2[i] = g_st[3][row]; ps3[i] = g_st[4][row]; ps4[i] = g_st[5][row];
        ps5[i] = g_st[6][row];
    }
    float wwloc[4];

    // ======== phase A: write addressing ========
    {
        float g = g_pw[b * 8 + 1], s0 = g_pw[b * 8 + 2], s1 = g_pw[b * 8 + 3];
        float s2 = g_pw[b * 8 + 4], gamma = g_pw[b * 8 + 5];

        float lm = __int_as_float(0xff800000);
        #pragma unroll
        for (int i = 0; i < 4; i++) {
            int n = t + 1024 * i;
            float v = g_score[b * NMEM + n];
            sc[n] = v; lm = fmaxf(lm, v);
        }
        lm = wredmax(lm);
        if (lane == 0) red[w] = lm;
        __syncthreads();
        if (w == 0) { float v = red[lane]; v = wredmax(v); if (lane == 0) bcast = v; }
        __syncthreads();
        float bm = bcast;

        float ls = 0.f;
        #pragma unroll
        for (int i = 0; i < 4; i++) {
            int n = t + 1024 * i;
            float pv = __expf(sc[n] - bm);
            sc[n] = pv; ls += pv;
        }
        ls = wredsum(ls);
        if (lane == 0) red[w] = ls;
        __syncthreads();
        if (w == 0) { float v = red[lane]; v = wredsum(v); if (lane == 0) bcast = v; }
        __syncthreads();
        float gZ = g / bcast, og = 1.f - g;

        #pragma unroll
        for (int i = 0; i < 4; i++) {
            int n = t + 1024 * i;
            wg[n] = fmaf(gZ, sc[n], og * ww0[b * NMEM + n]);
        }
        __syncthreads();

        float lp = 0.f;
        #pragma unroll
        for (int i = 0; i < 4; i++) {
            int n = t + 1024 * i;
            float wt = s0 * wg[(n - 1) & (NMEM - 1)] + s1 * wg[n] + s2 * wg[(n + 1) & (NMEM - 1)];
            float wp = (wt > 0.f) ? __powf(wt, gamma) : 0.f;
            sc[n] = wp; lp += wp;
        }
        lp = wredsum(lp);
        if (lane == 0) red[w] = lp;
        __syncthreads();
        if (w == 0) { float v = red[lane]; v = wredsum(v); if (lane == 0) bcast = v + 1e-16f; }
        __syncthreads();
        float iZp = 1.f / bcast;

        #pragma unroll
        for (int i = 0; i < 4; i++) {
            int n = t + 1024 * i;
            float wv = sc[n] * iZp;
            wwloc[i] = wv;
            g_ww[b * NMEM + n] = wv;
        }
    }

    // ======== phase B: read score from registers + read addressing ========
    {
        float beta = g_pr[b * 8 + 0], knr = g_pr[b * 8 + 6];
        float akr  = g_pr[b * 8 + 7], aa  = g_pw[b * 8 + 7];
        float g = g_pr[b * 8 + 1], s0 = g_pr[b * 8 + 2], s1 = g_pr[b * 8 + 3];
        float s2p = g_pr[b * 8 + 4], gamma = g_pr[b * 8 + 5];

        float lm = __int_as_float(0xff800000);
        #pragma unroll
        for (int i = 0; i < 4; i++) {
            int n = t + 1024 * i;
            float wwv = wwloc[i];
            float dot = pd1[i] - wwv * (pd2[i] - akr);
            float n2 = pss[i] + wwv * (2.f * (ps4[i] - ps2[i]))
                     + wwv * wwv * (ps3[i] - 2.f * ps5[i] + aa);
            float v = beta * dot / (sqrtf(fmaxf(n2, 0.f)) * knr + 1e-16f);
            sc[n] = v; lm = fmaxf(lm, v);
        }
        lm = wredmax(lm);
        if (lane == 0) red[w] = lm;
        __syncthreads();
        if (w == 0) { float v = red[lane]; v = wredmax(v); if (lane == 0) bcast = v; }
        __syncthreads();
        float bm = bcast;

        float ls = 0.f;
        #pragma unroll
        for (int i = 0; i < 4; i++) {
            int n = t + 1024 * i;
            float pv = __expf(sc[n] - bm);
            sc[n] = pv; ls += pv;
        }
        ls = wredsum(ls);
        if (lane == 0) red[w] = ls;
        __syncthreads();
        if (w == 0) { float v = red[lane]; v = wredsum(v); if (lane == 0) bcast = v; }
        __syncthreads();
        float gZ = g / bcast, og = 1.f - g;

        #pragma unroll
        for (int i = 0; i < 4; i++) {
            int n = t + 1024 * i;
            wg[n] = fmaf(gZ, sc[n], og * wr0[b * NMEM + n]);
        }
        __syncthreads();

        float lp = 0.f;
        #pragma unroll
        for (int i = 0; i < 4; i++) {
            int n = t + 1024 * i;
            float wt = s0 * wg[(n - 1) & (NMEM - 1)] + s1 * wg[n] + s2p * wg[(n + 1) & (NMEM - 1)];
            float wp = (wt > 0.f) ? __powf(wt, gamma) : 0.f;
            sc[n] = wp; lp += wp;
        }
        lp = wredsum(lp);
        if (lane == 0) red[w] = lp;
        __syncthreads();
        if (w == 0) { float v = red[lane]; v = wredsum(v); if (lane == 0) bcast = v + 1e-16f; }
        __syncthreads();
        float iZp = 1.f / bcast;

        #pragma unroll
        for (int i = 0; i < 4; i++) {
            int n = t + 1024 * i;
            g_wr[b * NMEM + n] = sc[n] * iZp;
        }
    }
}

// ============ Kernel 5: r partials = w_r . mem2 ============
__global__ void __launch_bounds__(256) k_readvec(const float* __restrict__ mem)
{
    __shared__ float es4[M], as4[M];
    __shared__ float part[16][M + 4];
    int b = blockIdx.x, chunk = blockIdx.y;
    int t = threadIdx.x;
    int m4 = t & 15;
    int rgrp = t >> 4;
    if (t < M) { es4[t] = g_e[b * M + t]; as4[t] = g_a[b * M + t]; }
    __syncthreads();

    int m = m4 * 4;
    float4 ev = make_float4(es4[m], es4[m + 1], es4[m + 2], es4[m + 3]);
    float4 av = make_float4(as4[m], as4[m + 1], as4[m + 2], as4[m + 3]);

    float4 acc = make_float4(0.f, 0.f, 0.f, 0.f);
    int n0 = chunk * 128;
    #pragma unroll
    for (int k = 0; k < 8; k++) {
        int n = n0 + rgrp + 16 * k;
        int row = b * NMEM + n;
        float wwv = g_ww[row], wrv = g_wr[row];
        float4 v = *(const float4*)(mem + (size_t)row * M + m);
        float4 v2;
        v2.x = fmaf(v.x, 1.f - wwv * ev.x, wwv * av.x);
        v2.y = fmaf(v.y, 1.f - wwv * ev.y, wwv * av.y);
        v2.z = fmaf(v.z, 1.f - wwv * ev.z, wwv * av.z);
        v2.w = fmaf(v.w, 1.f - wwv * ev.w, wwv * av.w);
        acc.x = fmaf(wrv, v2.x, acc.x);
        acc.y = fmaf(wrv, v2.y, acc.y);
        acc.z = fmaf(wrv, v2.z, acc.z);
        acc.w = fmaf(wrv, v2.w, acc.w);
    }
    *(float4*)&part[rgrp][m] = acc;
    __syncthreads();

    if (t < M) {
        float s = 0.f;
        #pragma unroll
        for (int r = 0; r < 16; r++) s += part[r][t];
        g_rpart[(b * 32 + chunk) * M + t] = s;
    }
}

// ============ Kernel 6: decoder ============
__global__ void k_decode(const float* __restrict__ decW, const float* __restrict__ decb,
                         float* __restrict__ out)
{
    __shared__ float xs[H];
    __shared__ float rs[M];
    int b = blockIdx.x, t = threadIdx.x;
    xs[t] = g_xm[b * H + t];
    if (t < M) {
        float s = 0.f;
        #pragma unroll
        for (int c = 0; c < 32; c++) s += g_rpart[(b * 32 + c) * M + t];
        rs[t] = s;
    }
    __syncthreads();
    if (t < OUT) {
        float acc = decb[t];
        for (int hh = 0; hh < H; hh++) acc = fmaf(xs[hh], decW[hh * OUT + t], acc);
        for (int m = 0; m < M; m++) acc = fmaf(rs[m], decW[(H + m) * OUT + t], acc);
        out[b * OUT + t] = acc;
    }
}

// ---------------- launch ----------------
extern "C" void kernel_launch(void* const* d_in, const int* in_sizes, int n_in,
                              void* d_out, int out_size)
{
    const float* x      = (const float*)d_in[0];
    const float* r0     = (const float*)d_in[1];
    const float* sr0    = (const float*)d_in[2];
    const float* si0    = (const float*)d_in[3];
    const float* w_r0   = (const float*)d_in[4];
    const float* w_w0   = (const float*)d_in[5];
    const float* mem    = (const float*)d_in[6];
    const float* encW   = (const float*)d_in[7];
    const float* encb   = (const float*)d_in[8];
    const float* log_dt = (const float*)d_in[9];
    const float* logAr  = (const float*)d_in[10];
    const float* Aim    = (const float*)d_in[11];
    const float* Cre    = (const float*)d_in[12];
    const float* Cim    = (const float*)d_in[13];
    const float* Dv     = (const float*)d_in[14];
    const float* decW   = (const float*)d_in[15];
    const float* decb   = (const float*)d_in[16];
    const float* readW  = (const float*)d_in[17];
    const float* readb  = (const float*)d_in[18];
    const float* writeW = (const float*)d_in[19];
    const float* writeb = (const float*)d_in[20];
    float* out = (float*)d_out;

    k_encode_scan<<<dim3(B, H / 16), 256>>>(x, r0, sr0, si0, encW, encb,
                                            log_dt, logAr, Aim, Cre, Cim, Dv);
    k_heads<<<B, 288>>>(writeW, writeb, readW, readb);
    k_pass1<<<512, 256>>>(mem);
    k_addr2<<<B, 1024>>>(w_w0, w_r0);
    k_readvec<<<dim3(B, 32), 256>>>(mem);
    k_decode<<<B, 256>>>(decW, decb, out);
}